// round 2
// baseline (speedup 1.0000x reference)
#include <cuda_runtime.h>

// RFCM loss, single-pass fused kernel.
// y_pred: [2,4,128,128,128] f32 (softmax applied), image: [2,1,128,128,128] f32.
// out: scalar f32.
//
// J1 mean = (1/(B*N)) * sum_{b,k} (C_bk - A_bk^2 / B_bk)
//   A=sum mem*img, B=sum mem, C=sum mem*img^2, mem = y_pred^2
// J2 per voxel = M*nbM - sum_k mem_k*nb_k, nb = 27-box-sum - center (zero pad)
//   (M = sum_k mem_k; nbM = sum_k nb_k by linearity)

#define D_ 128
#define HW 16384
#define NTOT 4194304.0   // B*N = 2*128^3

__device__ double g_acc[25];  // [0..7]=B(b,k) [8..15]=A [16..23]=C [24]=J2sum

__global__ void rfcm_init() {
    if (threadIdx.x < 25) g_acc[threadIdx.x] = 0.0;
}

// Shared layout (floats):
//   raw : 4 * 34*36   (per-k input plane with halo, padded stride 36)
//   xs  : 4 * 34*32   (per-k x-direction 3-sums)
//   ring: 4 * 3 *1024 (per-k 2D 9-sum planes, 3-slot z ring)
#define RAW_K 1224   // 34*36
#define XS_K  1088   // 34*32
#define SMEM_FLOATS (4*RAW_K + 4*XS_K + 12*1024)

__global__ __launch_bounds__(256, 2)
void rfcm_main(const float* __restrict__ ypred, const float* __restrict__ image) {
    extern __shared__ float sm[];
    float* raw  = sm;
    float* xs   = sm + 4 * RAW_K;
    float* ring = sm + 4 * RAW_K + 4 * XS_K;

    const int tid = threadIdx.x;
    const int lxi = tid & 31;        // x within tile
    const int wy  = tid >> 5;        // warp row (0..7)
    const int x0  = (blockIdx.x & 3) * 32;
    const int y0  = (blockIdx.x >> 2) * 32;
    const int zstart = blockIdx.y * 16;
    const int b = blockIdx.z;

    const float* yp_b = ypred + (size_t)b * 4 * D_ * HW;
    const float* im_b = image + (size_t)b * D_ * HW;

    float c_cur[16], c_next[16];     // center mem per (k, p)
    float accB[4] = {0,0,0,0}, accA[4] = {0,0,0,0}, accC[4] = {0,0,0,0};
    float accJ2 = 0.f;

    auto computePlane = [&](int zz, float* cdst) {
        const int slot = (zz + 3) % 3;
        if (zz < 0 || zz >= 128) {
            for (int i = tid; i < 4 * 1024; i += 256) {
                int k = i >> 10, j = i & 1023;
                ring[(k * 3 + slot) * 1024 + j] = 0.f;
            }
            __syncthreads();
            return;
        }
        // Load mem = pred^2 plane with halo, zero-padded.
        for (int i = tid; i < 4 * 1156; i += 256) {
            int k = i / 1156, j = i - k * 1156;
            int r = j / 34, c = j - r * 34;
            int gy = y0 - 1 + r, gx = x0 - 1 + c;
            float v = 0.f;
            if ((unsigned)gy < 128u && (unsigned)gx < 128u) {
                float p = yp_b[(size_t)(k * D_ + zz) * HW + gy * 128 + gx];
                v = p * p;
            }
            raw[k * RAW_K + r * 36 + c] = v;
        }
        __syncthreads();
        // Capture center values for owned voxels.
        #pragma unroll
        for (int k = 0; k < 4; k++)
            #pragma unroll
            for (int p = 0; p < 4; p++)
                cdst[k * 4 + p] = raw[k * RAW_K + (wy + 8 * p + 1) * 36 + (lxi + 1)];
        // x-direction 3-sums (34 rows x 32 cols per k).
        for (int i = tid; i < 4 * XS_K; i += 256) {
            int k = i / XS_K, j = i - k * XS_K;
            int r = j >> 5, c = j & 31;
            const float* rr = raw + k * RAW_K + r * 36 + c;
            xs[k * XS_K + j] = rr[0] + rr[1] + rr[2];
        }
        __syncthreads();
        // y-direction 3-sums -> 2D 9-sum plane into ring slot.
        for (int i = tid; i < 4096; i += 256) {
            int k = i >> 10, j = i & 1023;
            int ly = j >> 5, c = j & 31;
            const float* xr = xs + k * XS_K + ly * 32 + c;
            ring[(k * 3 + slot) * 1024 + j] = xr[0] + xr[32] + xr[64];
        }
        __syncthreads();
    };

    computePlane(zstart - 1, c_next);   // c_next is scratch here
    computePlane(zstart, c_cur);

    for (int z = zstart; z < zstart + 16; z++) {
        computePlane(z + 1, c_next);
        const int s0 = (z + 2) % 3;   // P(z-1)
        const int s1 = z % 3;         // P(z)
        const int s2 = (z + 1) % 3;   // P(z+1)
        #pragma unroll
        for (int p = 0; p < 4; p++) {
            int ly = wy + 8 * p;
            int gy = y0 + ly, gx = x0 + lxi;
            float img = im_b[(size_t)z * HW + gy * 128 + gx];
            int idx = ly * 32 + lxi;
            float memSum = 0.f, nbSum = 0.f, tt = 0.f;
            #pragma unroll
            for (int k = 0; k < 4; k++) {
                float s27 = ring[(k * 3 + s0) * 1024 + idx]
                          + ring[(k * 3 + s1) * 1024 + idx]
                          + ring[(k * 3 + s2) * 1024 + idx];
                float mc = c_cur[k * 4 + p];
                float nb = s27 - mc;          // 26-neighbor sum (excl. center)
                accB[k] += mc;
                accA[k] += mc * img;
                accC[k] += mc * img * img;
                memSum += mc; nbSum += nb; tt += mc * nb;
            }
            accJ2 += memSum * nbSum - tt;
        }
        #pragma unroll
        for (int i = 0; i < 16; i++) c_cur[i] = c_next[i];
    }

    // Block reduction: warp shuffle, warp leaders -> double atomics.
    #pragma unroll
    for (int k = 0; k < 4; k++) {
        float vB = accB[k], vA = accA[k], vC = accC[k];
        #pragma unroll
        for (int off = 16; off; off >>= 1) {
            vB += __shfl_xor_sync(0xffffffffu, vB, off);
            vA += __shfl_xor_sync(0xffffffffu, vA, off);
            vC += __shfl_xor_sync(0xffffffffu, vC, off);
        }
        if (lxi == 0) {
            atomicAdd(&g_acc[b * 4 + k],      (double)vB);
            atomicAdd(&g_acc[8 + b * 4 + k],  (double)vA);
            atomicAdd(&g_acc[16 + b * 4 + k], (double)vC);
        }
    }
    {
        float vJ = accJ2;
        #pragma unroll
        for (int off = 16; off; off >>= 1)
            vJ += __shfl_xor_sync(0xffffffffu, vJ, off);
        if (lxi == 0) atomicAdd(&g_acc[24], (double)vJ);
    }
}

__global__ void rfcm_finalize(float* out) {
    double j1 = 0.0;
    #pragma unroll
    for (int i = 0; i < 8; i++) {
        double Bv = g_acc[i], Av = g_acc[8 + i], Cv = g_acc[16 + i];
        j1 += Cv - Av * Av / Bv;
    }
    double inv = 1.0 / NTOT;
    out[0] = (float)(j1 * inv + 0.0008 * g_acc[24] * inv);
}

extern "C" void kernel_launch(void* const* d_in, const int* in_sizes, int n_in,
                              void* d_out, int out_size) {
    const float* ypred = (const float*)d_in[0];
    const float* image = (const float*)d_in[1];
    // Robustness: y_pred has 16.7M elems, image 4.2M. Swap if order differs.
    if (n_in >= 2 && in_sizes[0] < in_sizes[1]) {
        ypred = (const float*)d_in[1];
        image = (const float*)d_in[0];
    }
    float* out = (float*)d_out;

    static const size_t smem_bytes = SMEM_FLOATS * sizeof(float);
    cudaFuncSetAttribute(rfcm_main, cudaFuncAttributeMaxDynamicSharedMemorySize,
                         (int)smem_bytes);

    rfcm_init<<<1, 32>>>();
    rfcm_main<<<dim3(16, 8, 2), 256, smem_bytes>>>(ypred, image);
    rfcm_finalize<<<1, 1>>>(out);
}

// round 3
// speedup vs baseline: 2.2688x; 2.2688x over previous
#include <cuda_runtime.h>

// RFCM loss — single fused kernel.
// y_pred: [2,4,128,128,128] f32 (softmax applied), image: [2,1,128,128,128] f32.
// J1 mean = (1/(B*N)) * sum_{b,k} (C - A^2/B); A=sum(mem*img), B=sum(mem), C=sum(mem*img^2)
// J2 voxel = M*S27 - M^2 - sum_k mem_k*s27_k + sum_k mem_k^2  (s27 = 27-box-sum, zero pad)
// mem = y_pred^2.

#define FULLMASK 0xffffffffu

__device__ double g_acc[25];   // [0..7]=B(b,k) [8..15]=A [16..23]=C [24]=J2
__device__ unsigned int g_sem;

__device__ __forceinline__ float4 sq4(float4 p) {
    float4 m; m.x = p.x*p.x; m.y = p.y*p.y; m.z = p.z*p.z; m.w = p.w*p.w; return m;
}
__device__ __forceinline__ float4 add4(float4 a, float4 b) {
    float4 r; r.x=a.x+b.x; r.y=a.y+b.y; r.z=a.z+b.z; r.w=a.w+b.w; return r;
}

__global__ __launch_bounds__(512, 1)
void rfcm_kernel(const float* __restrict__ ypred, const float* __restrict__ image,
                 float* __restrict__ out) {
    // x 3-sum planes: 4 k-channels, 18 y-rows (halo), 32 float4 per row.
    __shared__ float4 s_xs[4][18][32];
    __shared__ float  s_red[16 * 13];

    const int tx  = threadIdx.x;         // 0..31 -> x chunk of 4
    const int ty  = threadIdx.y;         // 0..15 -> y row
    const int tid = ty * 32 + tx;
    const int y0  = blockIdx.x * 16;
    const int z0  = blockIdx.y * 16;
    const int b   = blockIdx.z;

    const float* yp_b = ypred + (size_t)b * 4 * 128 * 16384;
    const float* im_b = image + (size_t)b * 128 * 16384;

    float4 qA[4], qB[4], qC[4], cc[4], cn[4];
    float accB[4] = {0,0,0,0}, accA[4] = {0,0,0,0}, accC[4] = {0,0,0,0};
    float4 j2 = make_float4(0.f, 0.f, 0.f, 0.f);

    auto loadM = [&](int k, int zz, int gy) -> float4 {
        float4 p = make_float4(0.f, 0.f, 0.f, 0.f);
        if ((unsigned)gy < 128u)
            p = *(const float4*)(yp_b + (((size_t)(k * 128 + zz)) << 14) + (gy << 7) + (tx << 2));
        return sq4(p);
    };
    auto xsum = [&](float4 m) -> float4 {
        float lf = __shfl_up_sync(FULLMASK, m.w, 1);
        float rt = __shfl_down_sync(FULLMASK, m.x, 1);
        if (tx == 0)  lf = 0.f;
        if (tx == 31) rt = 0.f;
        float4 r;
        r.x = lf  + m.x + m.y;
        r.y = m.x + m.y + m.z;
        r.z = m.y + m.z + m.w;
        r.w = m.z + m.w + rt;
        return r;
    };
    // Build the 2D 9-sum plane at depth zz into q[k]; record center mem into cn[k].
    auto plane = [&](int zz, float4 (&q)[4]) {
        if ((unsigned)zz < 128u) {
            #pragma unroll
            for (int k = 0; k < 4; k++) {
                float4 m = loadM(k, zz, y0 + ty);
                cn[k] = m;
                s_xs[k][ty + 1][tx] = xsum(m);
            }
            if (ty == 0) {
                #pragma unroll
                for (int k = 0; k < 4; k++)
                    s_xs[k][0][tx] = xsum(loadM(k, zz, y0 - 1));
            }
            if (ty == 15) {
                #pragma unroll
                for (int k = 0; k < 4; k++)
                    s_xs[k][17][tx] = xsum(loadM(k, zz, y0 + 16));
            }
            __syncthreads();
            #pragma unroll
            for (int k = 0; k < 4; k++)
                q[k] = add4(add4(s_xs[k][ty][tx], s_xs[k][ty + 1][tx]), s_xs[k][ty + 2][tx]);
            __syncthreads();
        } else {
            #pragma unroll
            for (int k = 0; k < 4; k++) q[k] = make_float4(0.f, 0.f, 0.f, 0.f);
        }
    };

    plane(z0 - 1, qA);
    plane(z0,     qB);
    #pragma unroll
    for (int k = 0; k < 4; k++) cc[k] = cn[k];

    for (int zi = 0; zi < 16; zi++) {
        const int z = z0 + zi;
        plane(z + 1, qC);

        const float4 img = *(const float4*)(im_b + (((size_t)z) << 14) + ((y0 + ty) << 7) + (tx << 2));
        const float4 i2 = sq4(img);
        float4 M = make_float4(0.f,0.f,0.f,0.f);
        float4 S = make_float4(0.f,0.f,0.f,0.f);
        float4 X = make_float4(0.f,0.f,0.f,0.f);
        #pragma unroll
        for (int k = 0; k < 4; k++) {
            float4 s27 = add4(add4(qA[k], qB[k]), qC[k]);
            float4 mc = cc[k];
            accB[k] += (mc.x + mc.y) + (mc.z + mc.w);
            accA[k] += fmaf(mc.x, img.x, fmaf(mc.y, img.y, fmaf(mc.z, img.z, mc.w * img.w)));
            accC[k] += fmaf(mc.x, i2.x,  fmaf(mc.y, i2.y,  fmaf(mc.z, i2.z,  mc.w * i2.w)));
            M = add4(M, mc);
            S = add4(S, s27);
            X.x = fmaf(mc.x, s27.x - mc.x, X.x);
            X.y = fmaf(mc.y, s27.y - mc.y, X.y);
            X.z = fmaf(mc.z, s27.z - mc.z, X.z);
            X.w = fmaf(mc.w, s27.w - mc.w, X.w);
        }
        j2.x += fmaf(M.x, S.x - M.x, -X.x);
        j2.y += fmaf(M.y, S.y - M.y, -X.y);
        j2.z += fmaf(M.z, S.z - M.z, -X.z);
        j2.w += fmaf(M.w, S.w - M.w, -X.w);

        #pragma unroll
        for (int k = 0; k < 4; k++) { qA[k] = qB[k]; qB[k] = qC[k]; cc[k] = cn[k]; }
    }

    // ---- block reduction ----
    float vals[13];
    #pragma unroll
    for (int k = 0; k < 4; k++) { vals[k] = accB[k]; vals[4 + k] = accA[k]; vals[8 + k] = accC[k]; }
    vals[12] = (j2.x + j2.y) + (j2.z + j2.w);

    #pragma unroll
    for (int q = 0; q < 13; q++) {
        float v = vals[q];
        #pragma unroll
        for (int off = 16; off; off >>= 1) v += __shfl_xor_sync(FULLMASK, v, off);
        vals[q] = v;
    }
    const int wid = tid >> 5, lane = tid & 31;
    if (lane == 0) {
        #pragma unroll
        for (int q = 0; q < 13; q++) s_red[wid * 13 + q] = vals[q];
    }
    __syncthreads();
    if (tid < 13) {
        float s = 0.f;
        #pragma unroll
        for (int w = 0; w < 16; w++) s += s_red[w * 13 + tid];
        double* dst;
        if (tid < 4)       dst = &g_acc[b * 4 + tid];
        else if (tid < 8)  dst = &g_acc[8 + b * 4 + (tid - 4)];
        else if (tid < 12) dst = &g_acc[16 + b * 4 + (tid - 8)];
        else               dst = &g_acc[24];
        atomicAdd(dst, (double)s);
        __threadfence();
    }
    __syncthreads();

    // ---- last block finalizes and resets accumulators for the next replay ----
    if (tid == 0) {
        unsigned old = atomicAdd(&g_sem, 1u);
        if (old == 127u) {   // grid = 8*8*2 = 128 blocks
            volatile double* ga = g_acc;
            double j1 = 0.0;
            #pragma unroll
            for (int i = 0; i < 8; i++) {
                double Bv = ga[i], Av = ga[8 + i], Cv = ga[16 + i];
                j1 += Cv - Av * Av / Bv;
            }
            const double inv = 1.0 / 4194304.0;   // B*N
            out[0] = (float)(j1 * inv + 0.0008 * ga[24] * inv);
            #pragma unroll
            for (int i = 0; i < 25; i++) g_acc[i] = 0.0;
            g_sem = 0u;
        }
    }
}

extern "C" void kernel_launch(void* const* d_in, const int* in_sizes, int n_in,
                              void* d_out, int out_size) {
    const float* ypred = (const float*)d_in[0];
    const float* image = (const float*)d_in[1];
    if (n_in >= 2 && in_sizes[0] < in_sizes[1]) {  // robustness to input order
        ypred = (const float*)d_in[1];
        image = (const float*)d_in[0];
    }
    rfcm_kernel<<<dim3(8, 8, 2), dim3(32, 16)>>>(ypred, image, (float*)d_out);
}